// round 6
// baseline (speedup 1.0000x reference)
#include <cuda_runtime.h>
#include <cstdint>

// Problem shape (fixed by dataset)
#define N_MAX   50000
#define E_MAX   800000
#define EMB     128
#define KTOT    256     // NF + EMB

// ---------------- device scratch (static: no runtime allocation) -----------
__device__ int    g_deg[N_MAX];
__device__ int    g_off[N_MAX + 1];
__device__ int    g_rank[E_MAX];
__device__ int    g_eidx[E_MAX];
__device__ float4 g_aggr4[N_MAX * 32];    // [N][32] float4 = h_aggr

// ============================ CSR build ====================================
__global__ void zero_deg_kernel(int n) {
    int i = blockIdx.x * blockDim.x + threadIdx.x;
    if (i < n) g_deg[i] = 0;
}

__global__ void hist_rank_kernel(const int* __restrict__ dst, int e) {
    int i = blockIdx.x * blockDim.x + threadIdx.x;
    if (i < e) g_rank[i] = atomicAdd(&g_deg[dst[i]], 1);
}

__global__ void scan_kernel(int n) {
    const int T = 1024;
    int tid  = threadIdx.x;
    int lane = tid & 31;
    int wid  = tid >> 5;
    int C = (n + T - 1) / T;
    int s = tid * C;
    int e = min(s + C, n);

    int sum = 0;
    for (int i = s; i < e; i++) sum += g_deg[i];

    int v = sum;
    #pragma unroll
    for (int d = 1; d < 32; d <<= 1) {
        int t = __shfl_up_sync(0xffffffffu, v, d);
        if (lane >= d) v += t;
    }
    __shared__ int wsum[32];
    if (lane == 31) wsum[wid] = v;
    __syncthreads();
    if (wid == 0) {
        int w = wsum[lane];
        #pragma unroll
        for (int d = 1; d < 32; d <<= 1) {
            int t = __shfl_up_sync(0xffffffffu, w, d);
            if (lane >= d) w += t;
        }
        wsum[lane] = w;
    }
    __syncthreads();

    int excl = (v - sum) + (wid > 0 ? wsum[wid - 1] : 0);
    int run = excl;
    for (int i = s; i < e; i++) {
        g_off[i] = run;
        run += g_deg[i];
    }
    if (e == n) g_off[n] = run;
}

__global__ void scatter_kernel(const int* __restrict__ dst, int e) {
    int i = blockIdx.x * blockDim.x + threadIdx.x;
    if (i < e) g_eidx[g_off[dst[i]] + g_rank[i]] = i;
}

// ============================ GEMM tile =====================================
// Computes a 64-node x 128-col tile of A[64,128] @ Wpart[128c,128k]^T where
// Wpart = W[:, koff:koff+128]. EPI=0: raw store. EPI=1: += partial (in out),
// + bias, relu.
// Validated layout (R3/R4, rel_err 1.7e-7): sQ k-major [128][64] XOR-swizzled
// (slot ^= k4-index), sW c-major [128][68]; inner product via fma.rn.f32x2
// packed along m (2 nodes / instruction).

#define BM  64
#define SWS 68
#define SQ_WORDS (128 * 64)            // 8192 floats
#define SW_WORDS (EMB * SWS)           // 8704 floats
#define SMEM_BYTES ((SQ_WORDS + SW_WORDS) * 4)   // 67584 B

__device__ __forceinline__ void ffma2(unsigned long long& d,
                                      unsigned long long a,
                                      unsigned long long b) {
    asm("fma.rn.f32x2 %0, %1, %2, %0;" : "+l"(d) : "l"(a), "l"(b));
}

__device__ __forceinline__ unsigned long long dup2(float v) {
    unsigned long long r;
    asm("mov.b64 %0, {%1, %1};" : "=l"(r) : "r"(__float_as_uint(v)));
    return r;
}

template<int EPI>
__device__ __forceinline__ void gemm_tile(const float4* __restrict__ A4,
                                          const float*  __restrict__ W,
                                          const float*  __restrict__ bias,
                                          float* __restrict__ out,
                                          int n, int nb, int koff,
                                          float* sQ, float* sW) {
    int tid = threadIdx.x;

    // ---- stage A rows (k-major, swizzled) ----
    #pragma unroll
    for (int f = tid; f < BM * 32; f += 256) {   // 2048 float4
        int m  = f >> 5;
        int kq = f & 31;
        int node = nb + m;
        float4 v = make_float4(0.f, 0.f, 0.f, 0.f);
        if (node < n) v = A4[(size_t)node * 32 + kq];
        int off = (((m >> 2) ^ (kq & 15)) << 2) + (m & 3);
        int row = 4 * kq;
        sQ[(row + 0) * 64 + off] = v.x;
        sQ[(row + 1) * 64 + off] = v.y;
        sQ[(row + 2) * 64 + off] = v.z;
        sQ[(row + 3) * 64 + off] = v.w;
    }

    int tm = tid & 15;
    int tn = tid >> 4;
    int m0 = tm * 4;
    int c0 = tn * 8;

    unsigned long long acc[8][2];
    #pragma unroll
    for (int p = 0; p < 8; p++) { acc[p][0] = 0ULL; acc[p][1] = 0ULL; }

    for (int kc = 0; kc < 128; kc += 64) {
        __syncthreads();   // sQ/prev-sW-consumers done before restage
        #pragma unroll
        for (int f = tid; f < EMB * 16; f += 256) {   // 2048 float4
            int c  = f >> 4;
            int kq = f & 15;
            float4 w = *reinterpret_cast<const float4*>(
                W + (size_t)c * KTOT + koff + kc + kq * 4);
            *reinterpret_cast<float4*>(sW + c * SWS + kq * 4) = w;
        }
        __syncthreads();

        #pragma unroll 4
        for (int k4 = 0; k4 < 16; k4++) {
            int kk = k4 * 4;
            int kg = kc + kk;
            int sw = (tm ^ ((kg >> 2) & 15)) << 2;

            float4 q0 = *reinterpret_cast<const float4*>(sQ + (kg + 0) * 64 + sw);
            float4 q1 = *reinterpret_cast<const float4*>(sQ + (kg + 1) * 64 + sw);
            float4 q2 = *reinterpret_cast<const float4*>(sQ + (kg + 2) * 64 + sw);
            float4 q3 = *reinterpret_cast<const float4*>(sQ + (kg + 3) * 64 + sw);
            const unsigned long long* qp0 = reinterpret_cast<const unsigned long long*>(&q0);
            const unsigned long long* qp1 = reinterpret_cast<const unsigned long long*>(&q1);
            const unsigned long long* qp2 = reinterpret_cast<const unsigned long long*>(&q2);
            const unsigned long long* qp3 = reinterpret_cast<const unsigned long long*>(&q3);

            float4 w4[8];
            #pragma unroll
            for (int p = 0; p < 8; p++)
                w4[p] = *reinterpret_cast<const float4*>(sW + (c0 + p) * SWS + kk);

            #pragma unroll
            for (int p = 0; p < 8; p++) {
                unsigned long long b0 = dup2(w4[p].x);
                ffma2(acc[p][0], qp0[0], b0);
                ffma2(acc[p][1], qp0[1], b0);
                unsigned long long b1 = dup2(w4[p].y);
                ffma2(acc[p][0], qp1[0], b1);
                ffma2(acc[p][1], qp1[1], b1);
                unsigned long long b2 = dup2(w4[p].z);
                ffma2(acc[p][0], qp2[0], b2);
                ffma2(acc[p][1], qp2[1], b2);
                unsigned long long b3 = dup2(w4[p].w);
                ffma2(acc[p][0], qp3[0], b3);
                ffma2(acc[p][1], qp3[1], b3);
            }
        }
    }

    // ---- epilogue ----
    #pragma unroll
    for (int i = 0; i < 4; i++) {
        int node = nb + m0 + i;
        if (node >= n) continue;
        int pr = i >> 1;
        int hf = i & 1;
        float o[8];
        #pragma unroll
        for (int p = 0; p < 8; p++) {
            unsigned int lo, hi;
            asm("mov.b64 {%0, %1}, %2;" : "=r"(lo), "=r"(hi) : "l"(acc[p][pr]));
            o[p] = __uint_as_float(hf ? hi : lo);
        }
        float* orow = out + (size_t)node * EMB + c0;
        if (EPI == 1) {
            float4 p0 = *reinterpret_cast<const float4*>(orow);
            float4 p1 = *reinterpret_cast<const float4*>(orow + 4);
            o[0] = fmaxf(o[0] + p0.x + bias[c0 + 0], 0.f);
            o[1] = fmaxf(o[1] + p0.y + bias[c0 + 1], 0.f);
            o[2] = fmaxf(o[2] + p0.z + bias[c0 + 2], 0.f);
            o[3] = fmaxf(o[3] + p0.w + bias[c0 + 3], 0.f);
            o[4] = fmaxf(o[4] + p1.x + bias[c0 + 4], 0.f);
            o[5] = fmaxf(o[5] + p1.y + bias[c0 + 5], 0.f);
            o[6] = fmaxf(o[6] + p1.z + bias[c0 + 6], 0.f);
            o[7] = fmaxf(o[7] + p1.w + bias[c0 + 7], 0.f);
        }
        *reinterpret_cast<float4*>(orow)     = make_float4(o[0], o[1], o[2], o[3]);
        *reinterpret_cast<float4*>(orow + 4) = make_float4(o[4], o[5], o[6], o[7]);
    }
}

// =================== combined gather + GEMM1 kernel ========================
// Block role by index: r % 9 == 8 -> GEMM1 tile (x @ Wx^T -> out partial),
// else CSR-gather block (8 warps, 1 node each). DRAM-bound gather blocks and
// FMA-bound GEMM blocks co-reside on SMs -> pipes overlap.
__global__ void __launch_bounds__(256, 3)
gather_gemm1_kernel(const float4* __restrict__ h4,
                    const float4* __restrict__ x4,
                    const float*  __restrict__ W,
                    float* __restrict__ out, int n) {
    extern __shared__ float smem[];
    int r = blockIdx.x;

    if ((r % 9) == 8) {
        int gi = r / 9;
        gemm_tile<0>(x4, W, nullptr, out, n, gi * BM, 0,
                     smem, smem + SQ_WORDS);
        return;
    }

    int gb   = r - r / 9;            // gather-block index
    int warp = threadIdx.x >> 5;
    int lane = threadIdx.x & 31;
    int node = gb * 8 + warp;
    if (node >= n) return;

    int s = g_off[node];
    int e = g_off[node + 1];
    float4 a = make_float4(0.f, 0.f, 0.f, 0.f);
    int j = s;
    for (; j + 4 <= e; j += 4) {
        int e0 = __ldg(g_eidx + j + 0);
        int e1 = __ldg(g_eidx + j + 1);
        int e2 = __ldg(g_eidx + j + 2);
        int e3 = __ldg(g_eidx + j + 3);
        float4 v0 = __ldg(h4 + (size_t)e0 * 32 + lane);
        float4 v1 = __ldg(h4 + (size_t)e1 * 32 + lane);
        float4 v2 = __ldg(h4 + (size_t)e2 * 32 + lane);
        float4 v3 = __ldg(h4 + (size_t)e3 * 32 + lane);
        a.x += (v0.x + v1.x) + (v2.x + v3.x);
        a.y += (v0.y + v1.y) + (v2.y + v3.y);
        a.z += (v0.z + v1.z) + (v2.z + v3.z);
        a.w += (v0.w + v1.w) + (v2.w + v3.w);
    }
    for (; j < e; j++) {
        int e0 = __ldg(g_eidx + j);
        float4 v0 = __ldg(h4 + (size_t)e0 * 32 + lane);
        a.x += v0.x; a.y += v0.y; a.z += v0.z; a.w += v0.w;
    }
    g_aggr4[(size_t)node * 32 + lane] = a;
}

// =================== GEMM2: partial + h_aggr @ Wh^T + bias, relu ==========
__global__ void __launch_bounds__(256, 3)
gemm2_kernel(const float* __restrict__ W,
             const float* __restrict__ bias,
             float* __restrict__ out, int n) {
    extern __shared__ float smem[];
    gemm_tile<1>(g_aggr4, W, bias, out, n, blockIdx.x * BM, 128,
                 smem, smem + SQ_WORDS);
}

// ---------------- launch ----------------------------------------------------
extern "C" void kernel_launch(void* const* d_in, const int* in_sizes, int n_in,
                              void* d_out, int out_size) {
    const float* h        = (const float*)d_in[0];   // [E, 128]
    const float* x        = (const float*)d_in[1];   // [N, 128]
    const int*   edge_dst = (const int*)  d_in[2];   // [E] int32
    const float* W        = (const float*)d_in[3];   // [128, 256]
    const float* b        = (const float*)d_in[4];   // [128]
    float*       out      = (float*)d_out;           // [N, 128]

    int E = in_sizes[2];
    int N = in_sizes[1] / EMB;

    cudaFuncSetAttribute(gather_gemm1_kernel,
                         cudaFuncAttributeMaxDynamicSharedMemorySize, SMEM_BYTES);
    cudaFuncSetAttribute(gemm2_kernel,
                         cudaFuncAttributeMaxDynamicSharedMemorySize, SMEM_BYTES);

    int gemmBlocks = (N + BM - 1) / BM;      // 782
    int combined   = gemmBlocks * 9;         // 1-in-9 are GEMM1 tiles

    zero_deg_kernel<<<(N + 255) / 256, 256>>>(N);
    hist_rank_kernel<<<(E + 255) / 256, 256>>>(edge_dst, E);
    scan_kernel<<<1, 1024>>>(N);
    scatter_kernel<<<(E + 255) / 256, 256>>>(edge_dst, E);
    gather_gemm1_kernel<<<combined, 256, SMEM_BYTES>>>(
        reinterpret_cast<const float4*>(h),
        reinterpret_cast<const float4*>(x),
        W, out, N);
    gemm2_kernel<<<gemmBlocks, 256, SMEM_BYTES>>>(W, b, out, N);
}

// round 7
// speedup vs baseline: 1.4424x; 1.4424x over previous
#include <cuda_runtime.h>
#include <cuda_bf16.h>
#include <cstdint>

// Problem shape (fixed by dataset)
#define N_MAX   50000
#define E_MAX   800000
#define EMB     128
#define KTOT    256     // NF + EMB

// ---------------- device scratch (static: no runtime allocation) -----------
__device__ int      g_deg[N_MAX];
__device__ int      g_off[N_MAX + 1];
__device__ int      g_rank[E_MAX];
__device__ int      g_eidx[E_MAX];
__device__ float4   g_aggr4[N_MAX * 32];        // [N][32] float4 = h_aggr
__device__ uint32_t g_Whi[EMB * (KTOT / 2)];    // [128][128] bf16x2 words
__device__ uint32_t g_Wlo[EMB * (KTOT / 2)];

// ============================ CSR build ====================================
__global__ void zero_deg_kernel(int n) {
    int i = blockIdx.x * blockDim.x + threadIdx.x;
    if (i < n) g_deg[i] = 0;
}

__global__ void hist_rank_kernel(const int* __restrict__ dst, int e) {
    int i = blockIdx.x * blockDim.x + threadIdx.x;
    if (i < e) g_rank[i] = atomicAdd(&g_deg[dst[i]], 1);
}

__global__ void scan_kernel(int n) {
    const int T = 1024;
    int tid  = threadIdx.x;
    int lane = tid & 31;
    int wid  = tid >> 5;
    int C = (n + T - 1) / T;
    int s = tid * C;
    int e = min(s + C, n);

    int sum = 0;
    for (int i = s; i < e; i++) sum += g_deg[i];

    int v = sum;
    #pragma unroll
    for (int d = 1; d < 32; d <<= 1) {
        int t = __shfl_up_sync(0xffffffffu, v, d);
        if (lane >= d) v += t;
    }
    __shared__ int wsum[32];
    if (lane == 31) wsum[wid] = v;
    __syncthreads();
    if (wid == 0) {
        int w = wsum[lane];
        #pragma unroll
        for (int d = 1; d < 32; d <<= 1) {
            int t = __shfl_up_sync(0xffffffffu, w, d);
            if (lane >= d) w += t;
        }
        wsum[lane] = w;
    }
    __syncthreads();

    int excl = (v - sum) + (wid > 0 ? wsum[wid - 1] : 0);
    int run = excl;
    for (int i = s; i < e; i++) {
        g_off[i] = run;
        run += g_deg[i];
    }
    if (e == n) g_off[n] = run;
}

__global__ void scatter_kernel(const int* __restrict__ dst, int e) {
    int i = blockIdx.x * blockDim.x + threadIdx.x;
    if (i < e) g_eidx[g_off[dst[i]] + g_rank[i]] = i;
}

// ===================== bf16 split helpers ==================================
__device__ __forceinline__ uint32_t pk_bf2(float lo, float hi) {
    uint32_t r;
    asm("cvt.rn.bf16x2.f32 %0, %1, %2;" : "=r"(r) : "f"(hi), "f"(lo));
    return r;   // lower half = lo, upper = hi
}
__device__ __forceinline__ float2 unpk_bf2(uint32_t w) {
    __nv_bfloat162 b = *reinterpret_cast<__nv_bfloat162*>(&w);
    return __bfloat1622float2(b);
}
// split 2 floats into hi/lo bf16x2 words
__device__ __forceinline__ void split2(float a, float b,
                                       uint32_t& hi, uint32_t& lo) {
    hi = pk_bf2(a, b);
    float2 f = unpk_bf2(hi);
    lo = pk_bf2(a - f.x, b - f.y);
}

// --------------- W pre-conversion: f32 -> bf16 hi/lo words -----------------
__global__ void cvt_w_kernel(const float2* __restrict__ W2) {
    int i = blockIdx.x * blockDim.x + threadIdx.x;   // word index, 16384 total
    if (i >= EMB * (KTOT / 2)) return;
    float2 v = W2[i];
    uint32_t hi, lo;
    split2(v.x, v.y, hi, lo);
    g_Whi[i] = hi;
    g_Wlo[i] = lo;
}

// --------------------------- gather kernel ---------------------------------
// One warp per node, 16B per lane (512B row per edge), unroll 8 for MLP.
__global__ void __launch_bounds__(256)
gather_kernel(const float4* __restrict__ h4, int n) {
    int node = blockIdx.x * 8 + (threadIdx.x >> 5);
    int lane = threadIdx.x & 31;
    if (node >= n) return;

    int s = g_off[node];
    int e = g_off[node + 1];
    float4 a = make_float4(0.f, 0.f, 0.f, 0.f);
    int j = s;
    for (; j + 8 <= e; j += 8) {
        float4 v[8];
        #pragma unroll
        for (int u = 0; u < 8; u++) {
            int ei = __ldg(g_eidx + j + u);
            v[u] = __ldg(h4 + (size_t)ei * 32 + lane);
        }
        #pragma unroll
        for (int u = 0; u < 8; u++) {
            a.x += v[u].x; a.y += v[u].y; a.z += v[u].z; a.w += v[u].w;
        }
    }
    for (; j < e; j++) {
        int ei = __ldg(g_eidx + j);
        float4 v0 = __ldg(h4 + (size_t)ei * 32 + lane);
        a.x += v0.x; a.y += v0.y; a.z += v0.z; a.w += v0.w;
    }
    g_aggr4[(size_t)node * 32 + lane] = a;
}

// ===================== HMMA GEMM: out = relu(q @ W^T + b) ==================
// CTA = 64 nodes x 128 cols, 256 threads (8 warps: 2 m-groups x 4 n-groups,
// each warp 32m x 32n). K=256 processed in 4 chunks of 64.
// A (q = x|aggr) converted to bf16 hi/lo in-CTA; W read pre-converted.
// Split-precision: D += Ah*Wh + Ah*Wl + Al*Wh  (fp32 accum).
// smem rows padded to 36 words (32 data) -> fragment LDS banks (4r+kp) all
// distinct within a warp phase: conflict-free.

#define GM       64
#define ROWW     36                        // words per smem row
#define SA_W     (GM * ROWW)               // 2304 words
#define SW_W     (EMB * ROWW)              // 4608 words
#define GSMEM_W  (2 * SA_W + 2 * SW_W + EMB)   // + bias
#define GSMEM_B  (GSMEM_W * 4)             // 55808 B

__device__ __forceinline__ void mma_bf16(float4& d,
    uint32_t a0, uint32_t a1, uint32_t a2, uint32_t a3,
    uint32_t b0, uint32_t b1) {
    asm("mma.sync.aligned.m16n8k16.row.col.f32.bf16.bf16.f32 "
        "{%0,%1,%2,%3}, {%4,%5,%6,%7}, {%8,%9}, {%0,%1,%2,%3};"
        : "+f"(d.x), "+f"(d.y), "+f"(d.z), "+f"(d.w)
        : "r"(a0), "r"(a1), "r"(a2), "r"(a3), "r"(b0), "r"(b1));
}

__global__ void __launch_bounds__(256, 2)
gemm_kernel(const float4* __restrict__ x4,
            const float*  __restrict__ bias,
            float* __restrict__ out, int n) {
    extern __shared__ uint32_t sm[];
    uint32_t* sAh = sm;
    uint32_t* sAl = sm + SA_W;
    uint32_t* sWh = sm + 2 * SA_W;
    uint32_t* sWl = sm + 2 * SA_W + SW_W;
    float*    sB  = reinterpret_cast<float*>(sm + 2 * SA_W + 2 * SW_W);

    int tid  = threadIdx.x;
    int warp = tid >> 5;
    int lane = tid & 31;
    int g    = lane >> 2;      // group id (row within 8)
    int tig  = lane & 3;       // thread in group (k-pair / col-pair)
    int mw   = warp >> 2;      // 0..1
    int nw   = warp & 3;       // 0..3
    int m0   = mw * 32;
    int n0   = nw * 32;
    int nb   = blockIdx.x * GM;

    if (tid < EMB) sB[tid] = bias[tid];

    float4 acc[2][4];
    #pragma unroll
    for (int mt = 0; mt < 2; mt++)
        #pragma unroll
        for (int nt = 0; nt < 4; nt++)
            acc[mt][nt] = make_float4(0.f, 0.f, 0.f, 0.f);

    for (int kc = 0; kc < KTOT; kc += 64) {
        __syncthreads();
        // ---- stage A chunk: 64 rows x 16 float4, convert to hi/lo ----
        #pragma unroll
        for (int f = tid; f < GM * 16; f += 256) {
            int m = f >> 4;
            int q = f & 15;
            int node = nb + m;
            float4 v = make_float4(0.f, 0.f, 0.f, 0.f);
            if (node < n) {
                if (kc < 128) v = x4[(size_t)node * 32 + (kc >> 2) + q];
                else          v = g_aggr4[(size_t)node * 32 + ((kc - 128) >> 2) + q];
            }
            uint32_t h0, l0, h1, l1;
            split2(v.x, v.y, h0, l0);
            split2(v.z, v.w, h1, l1);
            int w = m * ROWW + q * 2;
            *reinterpret_cast<uint2*>(sAh + w) = make_uint2(h0, h1);
            *reinterpret_cast<uint2*>(sAl + w) = make_uint2(l0, l1);
        }
        // ---- stage W chunk: 128 rows x 8 uint4 (32 words) ----
        #pragma unroll
        for (int f = tid; f < EMB * 8; f += 256) {
            int c = f >> 3;
            int q = f & 7;
            int src = c * (KTOT / 2) + (kc >> 1) + q * 4;
            int dstw = c * ROWW + q * 4;
            *reinterpret_cast<uint4*>(sWh + dstw) =
                *reinterpret_cast<const uint4*>(g_Whi + src);
            *reinterpret_cast<uint4*>(sWl + dstw) =
                *reinterpret_cast<const uint4*>(g_Wlo + src);
        }
        __syncthreads();

        // ---- 4 k16 steps ----
        #pragma unroll
        for (int s = 0; s < 4; s++) {
            int so = s * 8 + tig;

            uint32_t ah[2][4], al[2][4];
            #pragma unroll
            for (int mt = 0; mt < 2; mt++) {
                int r0 = (m0 + mt * 16 + g) * ROWW;
                int r1 = r0 + 8 * ROWW;
                ah[mt][0] = sAh[r0 + so];
                ah[mt][1] = sAh[r1 + so];
                ah[mt][2] = sAh[r0 + so + 4];
                ah[mt][3] = sAh[r1 + so + 4];
                al[mt][0] = sAl[r0 + so];
                al[mt][1] = sAl[r1 + so];
                al[mt][2] = sAl[r0 + so + 4];
                al[mt][3] = sAl[r1 + so + 4];
            }
            uint32_t bh[4][2], bl[4][2];
            #pragma unroll
            for (int nt = 0; nt < 4; nt++) {
                int rn = (n0 + nt * 8 + g) * ROWW;
                bh[nt][0] = sWh[rn + so];
                bh[nt][1] = sWh[rn + so + 4];
                bl[nt][0] = sWl[rn + so];
                bl[nt][1] = sWl[rn + so + 4];
            }
            #pragma unroll
            for (int mt = 0; mt < 2; mt++)
                #pragma unroll
                for (int nt = 0; nt < 4; nt++) {
                    mma_bf16(acc[mt][nt],
                             ah[mt][0], ah[mt][1], ah[mt][2], ah[mt][3],
                             bh[nt][0], bh[nt][1]);
                    mma_bf16(acc[mt][nt],
                             ah[mt][0], ah[mt][1], ah[mt][2], ah[mt][3],
                             bl[nt][0], bl[nt][1]);
                    mma_bf16(acc[mt][nt],
                             al[mt][0], al[mt][1], al[mt][2], al[mt][3],
                             bh[nt][0], bh[nt][1]);
                }
        }
    }

    // ---- epilogue: bias + relu + store (float2 per fragment half) ----
    #pragma unroll
    for (int mt = 0; mt < 2; mt++) {
        int r0 = nb + m0 + mt * 16 + g;
        int r1 = r0 + 8;
        #pragma unroll
        for (int nt = 0; nt < 4; nt++) {
            int col = n0 + nt * 8 + tig * 2;
            float bx = sB[col], by = sB[col + 1];
            float4 a = acc[mt][nt];
            if (r0 < n) {
                float2 v = make_float2(fmaxf(a.x + bx, 0.f),
                                       fmaxf(a.y + by, 0.f));
                *reinterpret_cast<float2*>(out + (size_t)r0 * EMB + col) = v;
            }
            if (r1 < n) {
                float2 v = make_float2(fmaxf(a.z + bx, 0.f),
                                       fmaxf(a.w + by, 0.f));
                *reinterpret_cast<float2*>(out + (size_t)r1 * EMB + col) = v;
            }
        }
    }
}

// ---------------- launch ----------------------------------------------------
extern "C" void kernel_launch(void* const* d_in, const int* in_sizes, int n_in,
                              void* d_out, int out_size) {
    const float* h        = (const float*)d_in[0];   // [E, 128]
    const float* x        = (const float*)d_in[1];   // [N, 128]
    const int*   edge_dst = (const int*)  d_in[2];   // [E] int32
    const float* W        = (const float*)d_in[3];   // [128, 256]
    const float* b        = (const float*)d_in[4];   // [128]
    float*       out      = (float*)d_out;           // [N, 128]

    int E = in_sizes[2];
    int N = in_sizes[1] / EMB;

    cudaFuncSetAttribute(gemm_kernel,
                         cudaFuncAttributeMaxDynamicSharedMemorySize, GSMEM_B);

    zero_deg_kernel<<<(N + 255) / 256, 256>>>(N);
    hist_rank_kernel<<<(E + 255) / 256, 256>>>(edge_dst, E);
    scan_kernel<<<1, 1024>>>(N);
    scatter_kernel<<<(E + 255) / 256, 256>>>(edge_dst, E);
    cvt_w_kernel<<<(EMB * (KTOT / 2) + 255) / 256, 256>>>(
        reinterpret_cast<const float2*>(W));
    gather_kernel<<<(N + 7) / 8, 256>>>(
        reinterpret_cast<const float4*>(h), N);
    gemm_kernel<<<(N + GM - 1) / GM, 256, GSMEM_B>>>(
        reinterpret_cast<const float4*>(x), b, out, N);
}